// round 2
// baseline (speedup 1.0000x reference)
#include <cuda_runtime.h>

#define N_NODES 50000
#define KNBR 16
#define D 256
#define LN_EPS 1e-5f

// Scratch: aggregated (pre-GEMM) features g[n][d]  (51.2 MB, static device array)
__device__ float g_scratch[(size_t)N_NODES * D];

// ---------------------------------------------------------------------------
// Kernel A: g[n] = sum_k norm_w[n,k] * features[neighbors[n,k]]
// One block per node, 256 threads = one feature element each.
// ---------------------------------------------------------------------------
__global__ void gather_kernel(const float* __restrict__ feats,
                              const int* __restrict__ nbrs,
                              const float* __restrict__ iw,
                              int n)
{
    __shared__ float sw[KNBR];
    __shared__ int   snb[KNBR];
    const int node = blockIdx.x;
    const int tid  = threadIdx.x;

    if (tid < KNBR) {
        sw[tid]  = iw[(size_t)node * KNBR + tid];
        int ix   = nbrs[(size_t)node * KNBR + tid];
        // defensive clamp: if dtype assumption is wrong, fail on rel_err, not on a crash
        ix = ix < 0 ? 0 : (ix >= n ? n - 1 : ix);
        snb[tid] = ix;
    }
    __syncthreads();

    float wsum = 0.f;
#pragma unroll
    for (int k = 0; k < KNBR; k++) wsum += sw[k];

    float wn[KNBR];
    if (wsum == 0.f) {
#pragma unroll
        for (int k = 0; k < KNBR; k++) wn[k] = 1.0f / KNBR;
    } else {
        const float inv = 1.0f / wsum;
#pragma unroll
        for (int k = 0; k < KNBR; k++) wn[k] = sw[k] * inv;
    }

    float acc = 0.f;
#pragma unroll
    for (int k = 0; k < KNBR; k++)
        acc = fmaf(wn[k], feats[(size_t)snb[k] * D + tid], acc);

    g_scratch[(size_t)node * D + tid] = acc;
}

// ---------------------------------------------------------------------------
// Kernel B: out = LayerNorm(g @ W + b) * gamma + beta
// Tile: 64 rows x 256 cols (full output width) per block, 256 threads.
// Warp tm = tid/32 owns rows tm*8..tm*8+7; lane tn owns cols {tn*4..+3} and
// {128+tn*4..+3}. LN is a pure warp-shuffle reduction (row lives in one warp).
// ---------------------------------------------------------------------------
#define TM 64
#define TK 32

__global__ __launch_bounds__(256) void gemm_ln_kernel(
    const float* __restrict__ Wm,
    const float* __restrict__ bias,
    const float* __restrict__ gamma,
    const float* __restrict__ beta,
    float* __restrict__ out, int n)
{
    __shared__ float As[TM][TK];   // [m][k]
    __shared__ float Bs[TK][D];    // [k][c]

    const int tid = threadIdx.x;
    const int tm  = tid >> 5;    // warp id, 0..7
    const int tn  = tid & 31;    // lane,   0..31
    const int m0  = blockIdx.x * TM;
    const int cA  = tn * 4;       // first 4-col group
    const int cB  = 128 + tn * 4; // second 4-col group

    float acc[8][8];
    {
        float bb[8];
#pragma unroll
        for (int j = 0; j < 4; j++) { bb[j] = bias[cA + j]; bb[4 + j] = bias[cB + j]; }
#pragma unroll
        for (int i = 0; i < 8; i++)
#pragma unroll
            for (int j = 0; j < 8; j++) acc[i][j] = bb[j];
    }

    for (int kb = 0; kb < D; kb += TK) {
        // Load A tile: 64 rows x 32 cols (f4: 512 loads, 2 per thread)
        {
            const int r  = tid >> 3;          // 0..31
            const int c4 = (tid & 7) * 4;     // 0..28
#pragma unroll
            for (int rr = 0; rr < 2; rr++) {
                const int row = r + rr * 32;
                const int gr  = m0 + row;
                float4 v = make_float4(0.f, 0.f, 0.f, 0.f);
                if (gr < n)
                    v = *(const float4*)&g_scratch[(size_t)gr * D + kb + c4];
                *(float4*)&As[row][c4] = v;
            }
        }
        // Load B tile: 32 rows x 256 cols (f4: 2048 loads, 8 per thread)
#pragma unroll
        for (int t = 0; t < 8; t++) {
            const int idx = tid + t * 256;
            const int row = idx >> 6;
            const int c4  = (idx & 63) * 4;
            *(float4*)&Bs[row][c4] = *(const float4*)&Wm[(size_t)(kb + row) * D + c4];
        }
        __syncthreads();

#pragma unroll
        for (int k = 0; k < TK; k++) {
            float a[8];
#pragma unroll
            for (int i = 0; i < 8; i++) a[i] = As[tm * 8 + i][k];  // warp broadcast
            const float4 b0 = *(const float4*)&Bs[k][cA];  // 16B lane stride: conflict-free
            const float4 b1 = *(const float4*)&Bs[k][cB];
            const float bv[8] = { b0.x, b0.y, b0.z, b0.w, b1.x, b1.y, b1.z, b1.w };
#pragma unroll
            for (int i = 0; i < 8; i++)
#pragma unroll
                for (int j = 0; j < 8; j++)
                    acc[i][j] = fmaf(a[i], bv[j], acc[i][j]);
        }
        __syncthreads();
    }

    // Epilogue: LayerNorm per row + affine + store
    float gm[8], bt[8];
#pragma unroll
    for (int j = 0; j < 4; j++) {
        gm[j]     = gamma[cA + j];  gm[4 + j] = gamma[cB + j];
        bt[j]     = beta[cA + j];   bt[4 + j] = beta[cB + j];
    }

#pragma unroll
    for (int i = 0; i < 8; i++) {
        float s = 0.f, s2 = 0.f;
#pragma unroll
        for (int j = 0; j < 8; j++) { s += acc[i][j]; s2 = fmaf(acc[i][j], acc[i][j], s2); }
#pragma unroll
        for (int off = 16; off; off >>= 1) {
            s  += __shfl_xor_sync(0xffffffffu, s,  off);
            s2 += __shfl_xor_sync(0xffffffffu, s2, off);
        }
        const float mean = s * (1.0f / D);
        const float var  = fmaxf(s2 * (1.0f / D) - mean * mean, 0.f);
        const float rstd = rsqrtf(var + LN_EPS);

        const int r = m0 + tm * 8 + i;
        if (r < n) {
            float4 o0, o1;
            o0.x = (acc[i][0] - mean) * rstd * gm[0] + bt[0];
            o0.y = (acc[i][1] - mean) * rstd * gm[1] + bt[1];
            o0.z = (acc[i][2] - mean) * rstd * gm[2] + bt[2];
            o0.w = (acc[i][3] - mean) * rstd * gm[3] + bt[3];
            o1.x = (acc[i][4] - mean) * rstd * gm[4] + bt[4];
            o1.y = (acc[i][5] - mean) * rstd * gm[5] + bt[5];
            o1.z = (acc[i][6] - mean) * rstd * gm[6] + bt[6];
            o1.w = (acc[i][7] - mean) * rstd * gm[7] + bt[7];
            *(float4*)&out[(size_t)r * D + cA] = o0;
            *(float4*)&out[(size_t)r * D + cB] = o1;
        }
    }
}

// ---------------------------------------------------------------------------
extern "C" void kernel_launch(void* const* d_in, const int* in_sizes, int n_in,
                              void* d_out, int out_size)
{
    const float* feats = (const float*)d_in[0];
    const int*   nbrs  = (const int*)d_in[1];     // JAX int64 is silently int32 (x64 disabled)
    const float* iw    = (const float*)d_in[2];
    const float* Wm    = (const float*)d_in[3];
    const float* bias  = (const float*)d_in[4];
    const float* gam   = (const float*)d_in[5];
    const float* bet   = (const float*)d_in[6];
    float*       out   = (float*)d_out;

    const int n = in_sizes[0] / D;   // 50000

    gather_kernel<<<n, 256>>>(feats, nbrs, iw, n);
    gemm_ln_kernel<<<(n + TM - 1) / TM, 256>>>(Wm, bias, gam, bet, out, n);
}

// round 4
// speedup vs baseline: 1.4390x; 1.4390x over previous
#include <cuda_runtime.h>
#include <cuda_bf16.h>
#include <cstdint>

#define D       256
#define KNBR    16
#define MAXN    50000
#define LN_EPS  1e-5f
#define TILE_M  64
#define KCH     64
#define ROWP    72      // padded row pitch in bf16 elems (144 B) -> conflict-free ldmatrix

// ---------------- scratch (static device arrays; no allocations) ------------
__device__ __nv_bfloat16 g_hi[(size_t)MAXN * D];
__device__ __nv_bfloat16 g_lo[(size_t)MAXN * D];
__device__ __nv_bfloat16 wt_hi[D * D];   // [n][k] = W[k][n] hi part
__device__ __nv_bfloat16 wt_lo[D * D];   // [n][k] lo part

// ---------------- smem layout (bytes) ---------------------------------------
#define A_SPLIT_BYTES (TILE_M * ROWP * 2)          //  9216
#define B_SPLIT_BYTES (D * ROWP * 2)               // 36864
#define OFF_A_HI 0
#define OFF_A_LO (A_SPLIT_BYTES)
#define OFF_B_HI (2 * A_SPLIT_BYTES)
#define OFF_B_LO (2 * A_SPLIT_BYTES + B_SPLIT_BYTES)
#define STAGE    (2 * A_SPLIT_BYTES + 2 * B_SPLIT_BYTES)   // 92160
#define OFF_PAR  (2 * STAGE)                       // 184320 : bias|gamma|beta
#define OFF_REDS (OFF_PAR + 3 * D * 4)             // 187392 : [64][4] row sums
#define OFF_RED2 (OFF_REDS + TILE_M * 4 * 4)       // 188416 : [64][4] row sumsq
#define SMEM_TOTAL (OFF_RED2 + TILE_M * 4 * 4)     // 189440

// ---------------- helpers ---------------------------------------------------
__device__ __forceinline__ uint32_t smem_u32(const void* p) {
    uint32_t a;
    asm("{ .reg .u64 t; cvta.to.shared.u64 t, %1; cvt.u32.u64 %0, t; }"
        : "=r"(a) : "l"(p));
    return a;
}
__device__ __forceinline__ void cp16(uint32_t dst, const void* src, bool valid) {
    const int sz = valid ? 16 : 0;
    asm volatile("cp.async.cg.shared.global [%0], [%1], 16, %2;"
                 :: "r"(dst), "l"(src), "r"(sz));
}
__device__ __forceinline__ void ldm4(uint32_t* r, uint32_t addr) {
    asm volatile("ldmatrix.sync.aligned.m8n8.x4.shared.b16 {%0,%1,%2,%3}, [%4];"
                 : "=r"(r[0]), "=r"(r[1]), "=r"(r[2]), "=r"(r[3]) : "r"(addr));
}
__device__ __forceinline__ void mma16816(float* c, const uint32_t* a,
                                         uint32_t b0, uint32_t b1) {
    asm volatile("mma.sync.aligned.m16n8k16.row.col.f32.bf16.bf16.f32 "
                 "{%0,%1,%2,%3}, {%4,%5,%6,%7}, {%8,%9}, {%0,%1,%2,%3};"
                 : "+f"(c[0]), "+f"(c[1]), "+f"(c[2]), "+f"(c[3])
                 : "r"(a[0]), "r"(a[1]), "r"(a[2]), "r"(a[3]), "r"(b0), "r"(b1));
}

// ---------------------------------------------------------------------------
// Kernel 0: split + transpose W -> wt_hi/wt_lo [n][k]
// ---------------------------------------------------------------------------
__global__ void prep_w_kernel(const float* __restrict__ W)
{
    const int k = blockIdx.x;
    const int n = threadIdx.x;
    const float v = W[k * D + n];
    const __nv_bfloat16 h = __float2bfloat16(v);
    const __nv_bfloat16 l = __float2bfloat16(v - __bfloat162float(h));
    wt_hi[n * D + k] = h;
    wt_lo[n * D + k] = l;
}

// ---------------------------------------------------------------------------
// Kernel A: weighted gather, emits bf16 hi/lo split of g.
// 64 threads per node (float4 each), 4 nodes per 256-thread block.
// ---------------------------------------------------------------------------
__global__ __launch_bounds__(256) void gather_kernel(
    const float* __restrict__ feats,
    const int* __restrict__ nbrs,
    const float* __restrict__ iw,
    int n)
{
    __shared__ float sw[4][KNBR];
    __shared__ int   snb[4][KNBR];
    const int tid   = threadIdx.x;
    const int local = tid >> 6;
    const int t     = tid & 63;
    const int node  = blockIdx.x * 4 + local;

    if (t < KNBR && node < n) {
        sw[local][t] = iw[(size_t)node * KNBR + t];
        int ix = nbrs[(size_t)node * KNBR + t];
        ix = ix < 0 ? 0 : (ix >= n ? n - 1 : ix);
        snb[local][t] = ix;
    }
    __syncthreads();
    if (node >= n) return;

    float wsum = 0.f;
#pragma unroll
    for (int k = 0; k < KNBR; k++) wsum += sw[local][k];
    float wn[KNBR];
    if (wsum == 0.f) {
#pragma unroll
        for (int k = 0; k < KNBR; k++) wn[k] = 1.0f / KNBR;
    } else {
        const float inv = 1.0f / wsum;
#pragma unroll
        for (int k = 0; k < KNBR; k++) wn[k] = sw[local][k] * inv;
    }

    const float4* f4 = (const float4*)feats;
    float4 acc = make_float4(0.f, 0.f, 0.f, 0.f);
#pragma unroll
    for (int k = 0; k < KNBR; k++) {
        const float4 f = f4[(size_t)snb[local][k] * (D / 4) + t];
        const float w = wn[k];
        acc.x = fmaf(w, f.x, acc.x);
        acc.y = fmaf(w, f.y, acc.y);
        acc.z = fmaf(w, f.z, acc.z);
        acc.w = fmaf(w, f.w, acc.w);
    }

    float v[4] = {acc.x, acc.y, acc.z, acc.w};
    uint32_t ph[2], pl[2];
#pragma unroll
    for (int i = 0; i < 2; i++) {
        __nv_bfloat16 h0 = __float2bfloat16(v[2 * i]);
        __nv_bfloat16 h1 = __float2bfloat16(v[2 * i + 1]);
        __nv_bfloat16 l0 = __float2bfloat16(v[2 * i]     - __bfloat162float(h0));
        __nv_bfloat16 l1 = __float2bfloat16(v[2 * i + 1] - __bfloat162float(h1));
        ph[i] = ((uint32_t)__bfloat16_as_ushort(h1) << 16) | __bfloat16_as_ushort(h0);
        pl[i] = ((uint32_t)__bfloat16_as_ushort(l1) << 16) | __bfloat16_as_ushort(l0);
    }
    const size_t e = (size_t)node * D + t * 4;
    *(uint2*)&g_hi[e] = make_uint2(ph[0], ph[1]);
    *(uint2*)&g_lo[e] = make_uint2(pl[0], pl[1]);
}

// ---------------------------------------------------------------------------
// Kernel B: split-bf16 GEMM via mma.sync (m16n8k16), 3-pass (hi*hi+hi*lo+lo*hi),
// tile 64x256, K in 4 chunks of 64 with cp.async double-buffering,
// fused LayerNorm epilogue.
// Warp grid: 2 (M, 32 rows each) x 4 (N, 64 cols each).
// ---------------------------------------------------------------------------
__global__ __launch_bounds__(256, 1) void gemm_ln_mma_kernel(
    const float* __restrict__ bias,
    const float* __restrict__ gamma,
    const float* __restrict__ beta,
    float* __restrict__ out, int n)
{
    extern __shared__ char smem[];
    const uint32_t sb = smem_u32(smem);
    const int tid  = threadIdx.x;
    const int lane = tid & 31;
    const int wid  = tid >> 5;
    const int wm   = wid & 1;     // 0..1 -> rows wm*32..+31
    const int wn   = wid >> 1;    // 0..3 -> cols wn*64..+63
    const int m0   = blockIdx.x * TILE_M;

    // stage bias/gamma/beta
    {
        float* p = (float*)(smem + OFF_PAR);
        for (int i = tid; i < D; i += 256) {
            p[i]         = bias[i];
            p[D + i]     = gamma[i];
            p[2 * D + i] = beta[i];
        }
    }

    float acc[2][8][4];
#pragma unroll
    for (int t = 0; t < 2; t++)
#pragma unroll
        for (int j = 0; j < 8; j++)
#pragma unroll
            for (int q = 0; q < 4; q++) acc[t][j][q] = 0.f;

    // ldmatrix per-lane byte offsets
    const uint32_t a_lane = (uint32_t)(lane & 15) * (ROWP * 2) + (uint32_t)(lane >> 4) * 16;
    const uint32_t b_lane = (uint32_t)((lane & 7) + ((lane >> 4) << 3)) * (ROWP * 2)
                          + (uint32_t)((lane >> 3) & 1) * 16;

    // stage loader
    auto load_stage = [&](int st, int c) {
        const int k0 = c * KCH;
        const uint32_t base = sb + st * STAGE;
        // A: 2 splits x 64 rows x 4 chunks(16B) = 1024 -> 4/thread
#pragma unroll
        for (int i = 0; i < 4; i++) {
            const int idx = tid + i * 256;
            const int split = idx >> 9;
            const int r  = (idx >> 3) & 63;
            const int c8 = idx & 7;
            const int grow = m0 + r;
            const bool valid = grow < n;
            const int gr = valid ? grow : 0;
            const __nv_bfloat16* src = (split ? g_lo : g_hi) + (size_t)gr * D + k0 + c8 * 8;
            const uint32_t dst = base + (split ? OFF_A_LO : OFF_A_HI)
                               + (uint32_t)r * (ROWP * 2) + (uint32_t)c8 * 16;
            cp16(dst, src, valid);
        }
        // B: 2 splits x 256 rows x 4 chunks = 4096 -> 16/thread
#pragma unroll
        for (int i = 0; i < 16; i++) {
            const int idx = tid + i * 256;
            const int split = idx >> 11;
            const int r  = (idx >> 3) & 255;
            const int c8 = idx & 7;
            const __nv_bfloat16* src = (split ? wt_lo : wt_hi) + (size_t)r * D + k0 + c8 * 8;
            const uint32_t dst = base + (split ? OFF_B_LO : OFF_B_HI)
                               + (uint32_t)r * (ROWP * 2) + (uint32_t)c8 * 16;
            cp16(dst, src, true);
        }
        asm volatile("cp.async.commit_group;");
    };

    load_stage(0, 0);

#pragma unroll
    for (int c = 0; c < 4; c++) {
        if (c < 3) {
            load_stage((c + 1) & 1, c + 1);
            asm volatile("cp.async.wait_group 1;");
        } else {
            asm volatile("cp.async.wait_group 0;");
        }
        __syncthreads();

        const uint32_t base = sb + (uint32_t)(c & 1) * STAGE;
#pragma unroll
        for (int ks = 0; ks < 4; ks++) {
            uint32_t ah[2][4], al[2][4], bh[4][4], bl[4][4];
#pragma unroll
            for (int t = 0; t < 2; t++) {
                const uint32_t ao = base + (uint32_t)(wm * 32 + t * 16) * (ROWP * 2)
                                  + (uint32_t)ks * 32 + a_lane;
                ldm4(ah[t], ao + OFF_A_HI);
                ldm4(al[t], ao + OFF_A_LO);
            }
#pragma unroll
            for (int p = 0; p < 4; p++) {
                const uint32_t bo = base + (uint32_t)(wn * 64 + p * 16) * (ROWP * 2)
                                  + (uint32_t)ks * 32 + b_lane;
                ldm4(bh[p], bo + OFF_B_HI);
                ldm4(bl[p], bo + OFF_B_LO);
            }
#pragma unroll
            for (int t = 0; t < 2; t++)
#pragma unroll
                for (int j = 0; j < 8; j++) {
                    const uint32_t h0 = bh[j >> 1][(j & 1) * 2];
                    const uint32_t h1 = bh[j >> 1][(j & 1) * 2 + 1];
                    const uint32_t l0 = bl[j >> 1][(j & 1) * 2];
                    const uint32_t l1 = bl[j >> 1][(j & 1) * 2 + 1];
                    mma16816(acc[t][j], ah[t], h0, h1);   // hi*hi
                    mma16816(acc[t][j], ah[t], l0, l1);   // hi*lo
                    mma16816(acc[t][j], al[t], h0, h1);   // lo*hi
                }
        }
        __syncthreads();
    }

    // ---------------- fused LayerNorm epilogue -----------------------------
    const float* bias_s = (const float*)(smem + OFF_PAR);
    const float* gam_s  = bias_s + D;
    const float* bet_s  = bias_s + 2 * D;

    // add bias + per-thread row partials.  acc[t][j]{0,1}: row = l/4 (+t*16),
    // cols 2*(l%4)+{0,1}+j*8+wn*64; {2,3}: row +8.
    float s[4]  = {0.f, 0.f, 0.f, 0.f};
    float s2[4] = {0.f, 0.f, 0.f, 0.f};
#pragma unroll
    for (int t = 0; t < 2; t++)
#pragma unroll
        for (int j = 0; j < 8; j++)
#pragma unroll
            for (int q = 0; q < 4; q++) {
                const int col = wn * 64 + j * 8 + (lane & 3) * 2 + (q & 1);
                const float v = acc[t][j][q] + bias_s[col];
                acc[t][j][q] = v;
                const int slot = t * 2 + (q >> 1);
                s[slot] += v;
                s2[slot] = fmaf(v, v, s2[slot]);
            }
    // reduce over the 4 lanes sharing a row (xor 1,2 change only l%4)
#pragma unroll
    for (int slot = 0; slot < 4; slot++) {
        s[slot]  += __shfl_xor_sync(0xffffffffu, s[slot], 1);
        s2[slot] += __shfl_xor_sync(0xffffffffu, s2[slot], 1);
        s[slot]  += __shfl_xor_sync(0xffffffffu, s[slot], 2);
        s2[slot] += __shfl_xor_sync(0xffffffffu, s2[slot], 2);
    }
    float* redS  = (float*)(smem + OFF_REDS);
    float* redS2 = (float*)(smem + OFF_RED2);
    if ((lane & 3) == 0) {
#pragma unroll
        for (int slot = 0; slot < 4; slot++) {
            const int row = wm * 32 + (slot >> 1) * 16 + (slot & 1) * 8 + (lane >> 2);
            redS[row * 4 + wn]  = s[slot];
            redS2[row * 4 + wn] = s2[slot];
        }
    }
    __syncthreads();

#pragma unroll
    for (int slot = 0; slot < 4; slot++) {
        const int row = wm * 32 + (slot >> 1) * 16 + (slot & 1) * 8 + (lane >> 2);
        const float S  = redS[row * 4 + 0] + redS[row * 4 + 1]
                       + redS[row * 4 + 2] + redS[row * 4 + 3];
        const float Q  = redS2[row * 4 + 0] + redS2[row * 4 + 1]
                       + redS2[row * 4 + 2] + redS2[row * 4 + 3];
        const float mean = S * (1.0f / D);
        const float var  = fmaxf(Q * (1.0f / D) - mean * mean, 0.f);
        const float rstd = rsqrtf(var + LN_EPS);
        const int gr = m0 + row;
        if (gr < n) {
            const int t = slot >> 1, h = slot & 1;
#pragma unroll
            for (int j = 0; j < 8; j++) {
                const int col = wn * 64 + j * 8 + (lane & 3) * 2;
                float2 o;
                o.x = (acc[t][j][h * 2 + 0] - mean) * rstd * gam_s[col]     + bet_s[col];
                o.y = (acc[t][j][h * 2 + 1] - mean) * rstd * gam_s[col + 1] + bet_s[col + 1];
                *(float2*)&out[(size_t)gr * D + col] = o;
            }
        }
    }
}

// ---------------------------------------------------------------------------
extern "C" void kernel_launch(void* const* d_in, const int* in_sizes, int n_in,
                              void* d_out, int out_size)
{
    const float* feats = (const float*)d_in[0];
    const int*   nbrs  = (const int*)d_in[1];
    const float* iw    = (const float*)d_in[2];
    const float* Wm    = (const float*)d_in[3];
    const float* bias  = (const float*)d_in[4];
    const float* gam   = (const float*)d_in[5];
    const float* bet   = (const float*)d_in[6];
    float*       out   = (float*)d_out;

    const int n = in_sizes[0] / D;   // 50000

    cudaFuncSetAttribute(gemm_ln_mma_kernel,
                         cudaFuncAttributeMaxDynamicSharedMemorySize, SMEM_TOTAL);

    prep_w_kernel<<<D, D>>>(Wm);
    gather_kernel<<<(n + 3) / 4, 256>>>(feats, nbrs, iw, n);
    gemm_ln_mma_kernel<<<(n + TILE_M - 1) / TILE_M, 256, SMEM_TOTAL>>>(bias, gam, bet, out, n);
}